// round 3
// baseline (speedup 1.0000x reference)
#include <cuda_runtime.h>

// RecurrentGCN_87926570483780
//
// Reference math collapses exactly:
//   - K=1 DConv: edge data is dead code.
//   - H0 = zeros -> Z,R depend only on X; cell = (1-Z)*Ht.
//   - Final op: log_softmax over a size-1 axis == 0 identically.
// Output is EXACTLY zeros([N,1]) for all inputs.
//
// Round 3 experiment: the 4.9us is dominated by kernel-node launch/ramp
// overhead (issue=4.6%, DRAM=0%). Replace the kernel node with a graph
// MEMSET node (cudaMemsetAsync is capturable, allocation-free, async).
// float 0.0f is all-zero bytes, so memset(0) is bit-exact.

extern "C" void kernel_launch(void* const* d_in, const int* in_sizes, int n_in,
                              void* d_out, int out_size) {
    (void)d_in; (void)in_sizes; (void)n_in;
    cudaMemsetAsync(d_out, 0, (size_t)out_size * sizeof(float), 0);
}

// round 4
// speedup vs baseline: 1.5816x; 1.5816x over previous
#include <cuda_runtime.h>

// RecurrentGCN_87926570483780
//
// Reference math collapses exactly:
//   - K=1 DConv: edge data is dead code.
//   - H0 = zeros -> Z,R depend only on X; cell = (1-Z)*Ht.
//   - Final op: log_softmax over a size-1 axis == 0 identically.
// Output is EXACTLY zeros([N,1]) for all inputs.
//
// Round 4: memset node regressed (7.1us) -> back to a kernel node.
// Compress to a single CTA wave: 123 blocks x 256 threads, 2 x STG.128
// per thread (123*256*2 = 62976 float4 slots >= 62500). Fewer CTAs to
// dispatch -> shorter launch ramp; stores themselves are ~free.

__global__ void __launch_bounds__(256) zero_fill_wave(float4* __restrict__ out4, int n4) {
    int base = (blockIdx.x * blockDim.x + threadIdx.x) * 2;
    const float4 z = make_float4(0.f, 0.f, 0.f, 0.f);
    if (base + 1 < n4) {
        out4[base]     = z;
        out4[base + 1] = z;
    } else if (base < n4) {
        out4[base] = z;
    }
}

extern "C" void kernel_launch(void* const* d_in, const int* in_sizes, int n_in,
                              void* d_out, int out_size) {
    (void)d_in; (void)in_sizes; (void)n_in;

    int n4 = out_size >> 2;                    // 62500 (out_size % 4 == 0)
    int threads = 256;
    int per_block = threads * 2;               // float4 slots per block
    int blocks = (n4 + per_block - 1) / per_block;  // 123 -> single wave
    zero_fill_wave<<<blocks, threads>>>((float4*)d_out, n4);
}